// round 16
// baseline (speedup 1.0000x reference)
#include <cuda_runtime.h>
#include <cuda_bf16.h>
#include <cstdint>
#include <math.h>

// ===========================================================================
// DynamicMemoryBank — R15: R12 structure + per-warp k-phase staggering
//   (warps co-resident on an SMSP start their k-loops at opposite phases so
//    ldsm bursts and MMA bursts interleave across warps instead of colliding)
// ===========================================================================

__device__ __forceinline__ uint32_t smem_u32(const void* p) {
    uint32_t a;
    asm("{ .reg .u64 t; cvta.to.shared.u64 t, %1; cvt.u32.u64 %0, t; }" : "=r"(a) : "l"(p));
    return a;
}

#define LDSM_X4(R0, R1, R2, R3, ADDR) \
    asm volatile("ldmatrix.sync.aligned.m8n8.x4.shared.b16 {%0,%1,%2,%3}, [%4];" \
        : "=r"(R0), "=r"(R1), "=r"(R2), "=r"(R3) : "r"(ADDR))

#define LDSM_X4T(R0, R1, R2, R3, ADDR) \
    asm volatile("ldmatrix.sync.aligned.m8n8.x4.trans.shared.b16 {%0,%1,%2,%3}, [%4];" \
        : "=r"(R0), "=r"(R1), "=r"(R2), "=r"(R3) : "r"(ADDR))

#define MMA16816(C, A0, A1, A2, A3, B0, B1) \
    asm volatile("mma.sync.aligned.m16n8k16.row.col.f32.bf16.bf16.f32 " \
        "{%0,%1,%2,%3}, {%4,%5,%6,%7}, {%8,%9}, {%0,%1,%2,%3};" \
        : "+f"((C)[0]), "+f"((C)[1]), "+f"((C)[2]), "+f"((C)[3]) \
        : "r"(A0), "r"(A1), "r"(A2), "r"(A3), "r"(B0), "r"(B1))

#define CP_ASYNC16(DST, SRC) \
    asm volatile("cp.async.cg.shared.global [%0], [%1], 16;" :: "r"(DST), "l"(SRC))
#define CP_COMMIT() asm volatile("cp.async.commit_group;" ::: "memory")
#define CP_WAIT(N)  asm volatile("cp.async.wait_group %0;" :: "n"(N) : "memory")

// ---------------------------------------------------------------------------
// scratch
// ---------------------------------------------------------------------------
__device__ __nv_bfloat16 g_catb[33554432];    // [65536,512]
__device__ __nv_bfloat16 g_hb[67108864];      // [65536,1024]
__device__ __nv_bfloat16 g_memb[262144];      // [1024,256]
__device__ __nv_bfloat16 g_w1T[524288];       // [1024,512]
__device__ __nv_bfloat16 g_w2T[262144];       // [256,1024]
__device__ float         g_xpart[131072];     // [512,256] xmean partials (raw sums)
__device__ float         g_xmean[16384];      // [64,256]

// swizzled addr within a 128-row x 512B tile (16B-chunk granularity)
__device__ __forceinline__ uint32_t tile_addr(uint32_t base, int r, int colbyte) {
    return base + (uint32_t)(r * 512) + (uint32_t)(colbyte & ~127)
         + (uint32_t)(((((colbyte >> 4) & 7) ^ (r & 7)) << 4));
}

// ---------------------------------------------------------------------------
// Flash kernel: per CTA 128 rows of x; 8 mem chunks. Warp-phase-staggered.
// ---------------------------------------------------------------------------
__global__ void __launch_bounds__(256, 1)
flash_attn(const float* __restrict__ x, const __nv_bfloat16* __restrict__ memb,
           float* __restrict__ cat, __nv_bfloat16* __restrict__ catb,
           float* __restrict__ xpart)
{
    extern __shared__ char dsm[];
    const uint32_t dbase = smem_u32(dsm);
    const uint32_t sbase = (dbase + 1023) & ~1023u;
    const uint32_t xs = sbase;
    const uint32_t ms[2] = { sbase + 65536, sbase + 131072 };
    char* const sptr = dsm + (sbase - dbase);

    const int tid = threadIdx.x;
    const int wid = tid >> 5, lane = tid & 31;
    const int wphase = wid >> 2;     // 0 for warps 0-3, 1 for warps 4-7
    const long row0 = (long)blockIdx.x * 128;

    {
        const char* Mg = (const char*)memb;
#pragma unroll
        for (int j = 0; j < 16; j++) {
            int idx = tid + j * 256;
            int r = idx >> 5;
            int colbyte = (idx & 31) << 4;
            CP_ASYNC16(tile_addr(ms[0], r, colbyte), Mg + (long)r * 512 + colbyte);
        }
        CP_COMMIT();
    }

    {
        const float4* Xg = (const float4*)x + row0 * 64;
        float4* cat4  = (float4*)cat;
        uint2*  catb2 = (uint2*)catb;
        float4 csum = make_float4(0.f, 0.f, 0.f, 0.f);
#pragma unroll 8
        for (int it = 0; it < 32; it++) {
            int idx = it * 256 + tid;
            int r = idx >> 6;
            int c4 = idx & 63;
            float4 v = Xg[idx];
            cat4[(row0 + r) * 128 + c4] = v;
            __nv_bfloat162 lo = __float22bfloat162_rn(make_float2(v.x, v.y));
            __nv_bfloat162 hi = __float22bfloat162_rn(make_float2(v.z, v.w));
            uint2 pk = make_uint2(*reinterpret_cast<uint32_t*>(&lo),
                                  *reinterpret_cast<uint32_t*>(&hi));
            catb2[(row0 + r) * 128 + c4] = pk;
            int colbyte = c4 * 8;
            uint32_t addr = tile_addr(xs, r, colbyte & ~15) + (colbyte & 8);
            *(uint2*)(dsm + (addr - dbase)) = pk;
            csum.x += v.x; csum.y += v.y; csum.z += v.z; csum.w += v.w;
        }
        float4* red = (float4*)(sptr + 196608);
        red[tid] = csum;
        __syncthreads();
        if (tid < 64) {
            float4 a = red[tid], b = red[tid + 64], c = red[tid + 128], d = red[tid + 192];
            float4 s = make_float4(a.x + b.x + c.x + d.x, a.y + b.y + c.y + d.y,
                                   a.z + b.z + c.z + d.z, a.w + b.w + c.w + d.w);
            ((float4*)xpart)[blockIdx.x * 64 + tid] = s;
        }
    }

    float acc_o[32][4];
#pragma unroll
    for (int b = 0; b < 32; b++)
#pragma unroll
        for (int q = 0; q < 4; q++) acc_o[b][q] = 0.0f;
    float m0 = -1e30f, m1 = -1e30f, l0 = 0.0f, l1 = 0.0f;

    for (int c = 0; c < 8; c++) {
        const int b = c & 1;
        if (c + 1 < 8) {
            const char* Mg = (const char*)(memb + (long)(c + 1) * 128 * 256);
#pragma unroll
            for (int j = 0; j < 16; j++) {
                int idx = tid + j * 256;
                int r = idx >> 5;
                int colbyte = (idx & 31) << 4;
                CP_ASYNC16(tile_addr(ms[1 - b], r, colbyte), Mg + (long)r * 512 + colbyte);
            }
            CP_COMMIT();
            CP_WAIT(1);
        } else {
            CP_WAIT(0);
        }
        __syncthreads();

        float acc_s[16][4];
#pragma unroll
        for (int nb = 0; nb < 16; nb++)
#pragma unroll
            for (int q = 0; q < 4; q++) acc_s[nb][q] = 0.0f;

        const int kofs = wphase * 8;   // stagger SMSP co-residents by half
#pragma unroll
        for (int kk = 0; kk < 16; kk++) {
            const int ks = (kk + kofs) & 15;
            uint32_t a0, a1, a2, a3;
            {
                int r = 16 * wid + (lane & 15);
                int colbyte = ks * 32 + ((lane >> 4) << 4);
                LDSM_X4(a0, a1, a2, a3, tile_addr(xs, r, colbyte));
            }
#pragma unroll
            for (int nb2 = 0; nb2 < 8; nb2++) {
                uint32_t d0, d1, d2, d3;
                int rn = nb2 * 16 + (lane & 7) + ((lane >> 4) << 3);
                int colbyte = ks * 32 + (((lane >> 3) & 1) << 4);
                LDSM_X4(d0, d1, d2, d3, tile_addr(ms[b], rn, colbyte));
                MMA16816(acc_s[nb2 * 2],     a0, a1, a2, a3, d0, d1);
                MMA16816(acc_s[nb2 * 2 + 1], a0, a1, a2, a3, d2, d3);
            }
        }

        float rm0 = -1e30f, rm1 = -1e30f;
#pragma unroll
        for (int nb = 0; nb < 16; nb++) {
            rm0 = fmaxf(rm0, fmaxf(acc_s[nb][0], acc_s[nb][1]));
            rm1 = fmaxf(rm1, fmaxf(acc_s[nb][2], acc_s[nb][3]));
        }
        rm0 = fmaxf(rm0, __shfl_xor_sync(0xffffffffu, rm0, 1));
        rm0 = fmaxf(rm0, __shfl_xor_sync(0xffffffffu, rm0, 2));
        rm1 = fmaxf(rm1, __shfl_xor_sync(0xffffffffu, rm1, 1));
        rm1 = fmaxf(rm1, __shfl_xor_sync(0xffffffffu, rm1, 2));

        float mn0 = fmaxf(m0, rm0), mn1 = fmaxf(m1, rm1);
        float sc0 = __expf(m0 - mn0), sc1 = __expf(m1 - mn1);
        m0 = mn0; m1 = mn1;

        uint32_t pk[16], qk[16];
        float ls0 = 0.0f, ls1 = 0.0f;
#pragma unroll
        for (int nb = 0; nb < 16; nb++) {
            float e0 = __expf(acc_s[nb][0] - mn0);
            float e1 = __expf(acc_s[nb][1] - mn0);
            float e2 = __expf(acc_s[nb][2] - mn1);
            float e3 = __expf(acc_s[nb][3] - mn1);
            ls0 += e0 + e1; ls1 += e2 + e3;
            __nv_bfloat162 h0 = __float22bfloat162_rn(make_float2(e0, e1));
            __nv_bfloat162 h1 = __float22bfloat162_rn(make_float2(e2, e3));
            pk[nb] = *reinterpret_cast<uint32_t*>(&h0);
            qk[nb] = *reinterpret_cast<uint32_t*>(&h1);
        }
        ls0 += __shfl_xor_sync(0xffffffffu, ls0, 1);
        ls0 += __shfl_xor_sync(0xffffffffu, ls0, 2);
        ls1 += __shfl_xor_sync(0xffffffffu, ls1, 1);
        ls1 += __shfl_xor_sync(0xffffffffu, ls1, 2);
        l0 = l0 * sc0 + ls0;
        l1 = l1 * sc1 + ls1;

#pragma unroll
        for (int nb = 0; nb < 32; nb++) {
            acc_o[nb][0] *= sc0; acc_o[nb][1] *= sc0;
            acc_o[nb][2] *= sc1; acc_o[nb][3] *= sc1;
        }

        const int jofs = wphase * 4;
#pragma unroll
        for (int jj = 0; jj < 8; jj++) {
            const int j = (jj + jofs) & 7;
            uint32_t a0 = pk[2 * j], a1 = qk[2 * j], a2 = pk[2 * j + 1], a3 = qk[2 * j + 1];
#pragma unroll
            for (int on = 0; on < 16; on++) {
                uint32_t d0, d1, d2, d3;
                int grp = lane >> 3;
                int rv = 16 * j + ((grp & 1) << 3) + (lane & 7);
                int colbyte = on * 32 + ((grp >> 1) << 4);
                LDSM_X4T(d0, d1, d2, d3, tile_addr(ms[b], rv, colbyte));
                MMA16816(acc_o[on * 2],     a0, a1, a2, a3, d0, d1);
                MMA16816(acc_o[on * 2 + 1], a0, a1, a2, a3, d2, d3);
            }
        }
        __syncthreads();
    }

    float inv0 = 1.0f / l0, inv1 = 1.0f / l1;
    long r0 = row0 + 16 * wid + (lane >> 2);
    long r1 = r0 + 8;
#pragma unroll
    for (int nb = 0; nb < 32; nb++) {
        int cn = 256 + nb * 8 + (lane & 3) * 2;
        float v0 = acc_o[nb][0] * inv0, v1 = acc_o[nb][1] * inv0;
        float v2 = acc_o[nb][2] * inv1, v3 = acc_o[nb][3] * inv1;
        *(float2*)(cat + r0 * 512 + cn) = make_float2(v0, v1);
        *(float2*)(cat + r1 * 512 + cn) = make_float2(v2, v3);
        __nv_bfloat162 h0 = __float22bfloat162_rn(make_float2(v0, v1));
        __nv_bfloat162 h1 = __float22bfloat162_rn(make_float2(v2, v3));
        *(uint32_t*)(catb + r0 * 512 + cn) = *reinterpret_cast<uint32_t*>(&h0);
        *(uint32_t*)(catb + r1 * 512 + cn) = *reinterpret_cast<uint32_t*>(&h1);
    }
}

// ---------------------------------------------------------------------------
// G3: h = silu(catb @ w1T^T + b1) -> bf16. R12 2-stage + warp phase stagger.
// ---------------------------------------------------------------------------
__global__ void __launch_bounds__(256, 2)
gemm_g3(const __nv_bfloat16* __restrict__ A, const __nv_bfloat16* __restrict__ B,
        const float* __restrict__ bias, __nv_bfloat16* __restrict__ Cb,
        int K, int ldcb)
{
    extern __shared__ char dsm[];
    const uint32_t sbase = (smem_u32(dsm) + 1023) & ~1023u;
    const int tid = threadIdx.x;
    const int wid = tid >> 5, lane = tid & 31;
    const int wm = wid & 3;
    const int wn = wid >> 2;
    const int kofs = (wid >> 2) << 1;   // 0 or 2: SMSP co-residents opposite phase
    const long row0 = (long)blockIdx.y * 128;
    const long col0 = (long)blockIdx.x * 128;

    const uint32_t sA[2] = { sbase,         sbase + 32768 };
    const uint32_t sB[2] = { sbase + 16384, sbase + 49152 };

    float acc[2][8][4];
#pragma unroll
    for (int i = 0; i < 2; i++)
#pragma unroll
        for (int j = 0; j < 8; j++)
#pragma unroll
            for (int q = 0; q < 4; q++) acc[i][j][q] = 0.0f;

    const char* Ag = (const char*)(A + row0 * K);
    const char* Bg = (const char*)(B + col0 * K);
    const long rowb = (long)K * 2;
    const int lr = tid >> 3;
    const int lc = tid & 7;
    const int nchunks = K >> 6;

    {
#pragma unroll
        for (int j = 0; j < 4; j++) {
            int r = lr + j * 32;
            uint32_t off = (uint32_t)(r * 128) + (uint32_t)((lc ^ (r & 7)) << 4);
            CP_ASYNC16(sA[0] + off, Ag + (long)r * rowb + lc * 16);
            CP_ASYNC16(sB[0] + off, Bg + (long)r * rowb + lc * 16);
        }
        CP_COMMIT();
    }

    for (int i = 0; i < nchunks; i++) {
        const int b = i & 1;
        if (i + 1 < nchunks) {
            const long kb = (long)(i + 1) << 7;
#pragma unroll
            for (int j = 0; j < 4; j++) {
                int r = lr + j * 32;
                uint32_t off = (uint32_t)(r * 128) + (uint32_t)((lc ^ (r & 7)) << 4);
                CP_ASYNC16(sA[1 - b] + off, Ag + (long)r * rowb + kb + lc * 16);
                CP_ASYNC16(sB[1 - b] + off, Bg + (long)r * rowb + kb + lc * 16);
            }
            CP_COMMIT();
            CP_WAIT(1);
        } else {
            CP_WAIT(0);
        }
        __syncthreads();

#pragma unroll
        for (int kk = 0; kk < 4; kk++) {
            const int ks = (kk + kofs) & 3;
            uint32_t af[2][4];
#pragma unroll
            for (int mi = 0; mi < 2; mi++) {
                int r = wm * 32 + mi * 16 + (lane & 15);
                int cch = ks * 2 + (lane >> 4);
                uint32_t addr = sA[b] + (uint32_t)(r * 128) + (uint32_t)((cch ^ (r & 7)) << 4);
                LDSM_X4(af[mi][0], af[mi][1], af[mi][2], af[mi][3], addr);
            }
            uint32_t bf[4][4];
#pragma unroll
            for (int nt = 0; nt < 4; nt++) {
                int r = wn * 64 + nt * 16 + (lane & 7) + ((lane >> 4) << 3);
                int cch = ks * 2 + ((lane >> 3) & 1);
                uint32_t addr = sB[b] + (uint32_t)(r * 128) + (uint32_t)((cch ^ (r & 7)) << 4);
                LDSM_X4(bf[nt][0], bf[nt][1], bf[nt][2], bf[nt][3], addr);
            }
#pragma unroll
            for (int mi = 0; mi < 2; mi++)
#pragma unroll
                for (int ni = 0; ni < 8; ni++) {
                    uint32_t b0 = bf[ni >> 1][(ni & 1) * 2];
                    uint32_t b1 = bf[ni >> 1][(ni & 1) * 2 + 1];
                    MMA16816(acc[mi][ni], af[mi][0], af[mi][1], af[mi][2], af[mi][3], b0, b1);
                }
        }
        __syncthreads();
    }

#pragma unroll
    for (int mi = 0; mi < 2; mi++) {
#pragma unroll
        for (int h = 0; h < 2; h++) {
            long r = row0 + wm * 32 + mi * 16 + (lane >> 2) + h * 8;
#pragma unroll
            for (int ni = 0; ni < 8; ni++) {
                int cn = (int)col0 + wn * 64 + ni * 8 + (lane & 3) * 2;
                float v0 = acc[mi][ni][h * 2]     + bias[cn];
                float v1 = acc[mi][ni][h * 2 + 1] + bias[cn + 1];
                v0 = v0 / (1.0f + __expf(-v0));
                v1 = v1 / (1.0f + __expf(-v1));
                __nv_bfloat162 h2 = __float22bfloat162_rn(make_float2(v0, v1));
                *(uint32_t*)(Cb + r * ldcb + cn) = *reinterpret_cast<uint32_t*>(&h2);
            }
        }
    }
}

// ---------------------------------------------------------------------------
// G4: g = sigmoid(hb @ w2T^T + b2), 128 rows (64 b x 2 m) x 128 c tile.
// R12 2-stage + warp phase stagger. In-CTA b-reduce -> newmem.
// ---------------------------------------------------------------------------
__global__ void __launch_bounds__(256, 2)
gemm_g4(const __nv_bfloat16* __restrict__ A, const __nv_bfloat16* __restrict__ B,
        const float* __restrict__ bias,
        const float* __restrict__ mem, const float* __restrict__ xm,
        float* __restrict__ nm)
{
    extern __shared__ char dsm[];
    const uint32_t sbase = (smem_u32(dsm) + 1023) & ~1023u;
    const int tid = threadIdx.x;
    const int wid = tid >> 5, lane = tid & 31;
    const int wm = wid & 3;
    const int wn = wid >> 2;
    const int kofs = (wid >> 2) << 1;
    const int m0 = blockIdx.y * 2;
    const int col0 = blockIdx.x * 128;
    const int K = 1024;

    const uint32_t sA[2] = { sbase,         sbase + 32768 };
    const uint32_t sB[2] = { sbase + 16384, sbase + 49152 };

    float acc[2][8][4];
#pragma unroll
    for (int i = 0; i < 2; i++)
#pragma unroll
        for (int j = 0; j < 8; j++)
#pragma unroll
            for (int q = 0; q < 4; q++) acc[i][j][q] = 0.0f;

    const char* Ag = (const char*)A;
    const char* Bg = (const char*)(B + (long)col0 * K);
    const long rowb = (long)K * 2;
    const int lr = tid >> 3;
    const int lc = tid & 7;
    const int nchunks = K >> 6;

#pragma unroll
    for (int j = 0; j < 4; j++) {
        int i = lr + j * 32;
        long gr = ((long)(i & 63) << 10) + m0 + (i >> 6);
        uint32_t off = (uint32_t)(i * 128) + (uint32_t)((lc ^ (i & 7)) << 4);
        CP_ASYNC16(sA[0] + off, Ag + gr * rowb + lc * 16);
        CP_ASYNC16(sB[0] + off, Bg + (long)i * rowb + lc * 16);
    }
    CP_COMMIT();

    for (int it = 0; it < nchunks; it++) {
        const int b = it & 1;
        if (it + 1 < nchunks) {
            const long kb = (long)(it + 1) << 7;
#pragma unroll
            for (int j = 0; j < 4; j++) {
                int i = lr + j * 32;
                long gr = ((long)(i & 63) << 10) + m0 + (i >> 6);
                uint32_t off = (uint32_t)(i * 128) + (uint32_t)((lc ^ (i & 7)) << 4);
                CP_ASYNC16(sA[1 - b] + off, Ag + gr * rowb + kb + lc * 16);
                CP_ASYNC16(sB[1 - b] + off, Bg + (long)i * rowb + kb + lc * 16);
            }
            CP_COMMIT();
            CP_WAIT(1);
        } else {
            CP_WAIT(0);
        }
        __syncthreads();

#pragma unroll
        for (int kk = 0; kk < 4; kk++) {
            const int ks = (kk + kofs) & 3;
            uint32_t af[2][4];
#pragma unroll
            for (int mi = 0; mi < 2; mi++) {
                int r = wm * 32 + mi * 16 + (lane & 15);
                int cch = ks * 2 + (lane >> 4);
                uint32_t addr = sA[b] + (uint32_t)(r * 128) + (uint32_t)((cch ^ (r & 7)) << 4);
                LDSM_X4(af[mi][0], af[mi][1], af[mi][2], af[mi][3], addr);
            }
            uint32_t bf[4][4];
#pragma unroll
            for (int nt = 0; nt < 4; nt++) {
                int r = wn * 64 + nt * 16 + (lane & 7) + ((lane >> 4) << 3);
                int cch = ks * 2 + ((lane >> 3) & 1);
                uint32_t addr = sB[b] + (uint32_t)(r * 128) + (uint32_t)((cch ^ (r & 7)) << 4);
                LDSM_X4(bf[nt][0], bf[nt][1], bf[nt][2], bf[nt][3], addr);
            }
#pragma unroll
            for (int mi = 0; mi < 2; mi++)
#pragma unroll
                for (int ni = 0; ni < 8; ni++) {
                    uint32_t b0 = bf[ni >> 1][(ni & 1) * 2];
                    uint32_t b1 = bf[ni >> 1][(ni & 1) * 2 + 1];
                    MMA16816(acc[mi][ni], af[mi][0], af[mi][1], af[mi][2], af[mi][3], b0, b1);
                }
        }
        __syncthreads();
    }

    // ---- epilogue: blend into padded smem (528B rows), reduce over b ----
#pragma unroll
    for (int mi = 0; mi < 2; mi++) {
#pragma unroll
        for (int h = 0; h < 2; h++) {
            int il = wm * 32 + mi * 16 + (lane >> 2) + h * 8;
            int bb = il & 63;
            int mloc = il >> 6;
#pragma unroll
            for (int ni = 0; ni < 8; ni++) {
                int cl = wn * 64 + ni * 8 + (lane & 3) * 2;
                int cn = col0 + cl;
                float v0 = acc[mi][ni][h * 2]     + bias[cn];
                float v1 = acc[mi][ni][h * 2 + 1] + bias[cn + 1];
                float g0 = 1.0f / (1.0f + __expf(-v0));
                float g1 = 1.0f / (1.0f + __expf(-v1));
                float mm0 = mem[(m0 + mloc) * 256 + cn];
                float mm1 = mem[(m0 + mloc) * 256 + cn + 1];
                float xv0 = xm[bb * 256 + cn];
                float xv1 = xm[bb * 256 + cn + 1];
                float o0 = fmaf(xv0 - mm0, g0, mm0) * (1.0f / 64.0f);
                float o1 = fmaf(xv1 - mm1, g1, mm1) * (1.0f / 64.0f);
                *(float2*)(dsm + (sbase - smem_u32(dsm)) + il * 528 + cl * 4) = make_float2(o0, o1);
            }
        }
    }
    __syncthreads();

    {
        int mloc = tid >> 7;
        int c = tid & 127;
        const char* sred = dsm + (sbase - smem_u32(dsm));
        float s = 0.0f;
#pragma unroll
        for (int k = 0; k < 64; k++) {
            int il = mloc * 64 + k;
            s += *(const float*)(sred + il * 528 + c * 4);
        }
        nm[(m0 + mloc) * 256 + col0 + c] = s;
    }
}

// ---------------------------------------------------------------------------
// merged weight conversions (memb + w1T + w2T)
// ---------------------------------------------------------------------------
__global__ void conv_all(const float* __restrict__ mem, const float* __restrict__ w1,
                         const float* __restrict__ w2,
                         __nv_bfloat16* __restrict__ memb, __nv_bfloat16* __restrict__ w1T,
                         __nv_bfloat16* __restrict__ w2T)
{
    int i = blockIdx.x * 256 + threadIdx.x;   // 0..524287
    {
        int k = i >> 10, n = i & 1023;
        w1T[n * 512 + k] = __float2bfloat16(w1[i]);
    }
    if (i < 262144) {
        memb[i] = __float2bfloat16(mem[i]);
        int f = i >> 8, c = i & 255;
        w2T[c * 1024 + f] = __float2bfloat16(w2[i]);
    }
}

// combine xmean partials (raw sums -> mean)
__global__ void xmean_comb(const float* __restrict__ xpart, float* __restrict__ xmn)
{
    int i = blockIdx.x * 256 + threadIdx.x;   // 0..16383
    int b = i >> 8, c = i & 255;
    float s = 0.0f;
#pragma unroll
    for (int k = 0; k < 8; k++) s += xpart[(b * 8 + k) * 256 + c];
    xmn[i] = s * (1.0f / 1024.0f);
}

// ---------------------------------------------------------------------------
extern "C" void kernel_launch(void* const* d_in, const int* in_sizes, int n_in,
                              void* d_out, int out_size)
{
    const float* x      = (const float*)d_in[0];
    const float* memory = (const float*)d_in[1];
    const float* w1     = (const float*)d_in[2];
    const float* b1     = (const float*)d_in[3];
    const float* w2     = (const float*)d_in[4];
    const float* b2     = (const float*)d_in[5];

    float* out    = (float*)d_out;
    float* cat    = out;               // [65536,512]
    float* newmem = out + 33554432ll;  // [1024,256]

    __nv_bfloat16 *catb, *hb, *memb, *w1T, *w2T;
    float *xp, *xmn;
    cudaGetSymbolAddress((void**)&catb, g_catb);
    cudaGetSymbolAddress((void**)&hb, g_hb);
    cudaGetSymbolAddress((void**)&memb, g_memb);
    cudaGetSymbolAddress((void**)&w1T, g_w1T);
    cudaGetSymbolAddress((void**)&w2T, g_w2T);
    cudaGetSymbolAddress((void**)&xp, g_xpart);
    cudaGetSymbolAddress((void**)&xmn, g_xmean);

    const int SMEM_G3 = 1024 + 65536;           // guard + 2x(16KB+16KB)
    const int SMEM_G4 = 1024 + 128 * 528;       // guard + max(tiles, reduce buf)
    const int SMEM_F  = 1024 + 3 * 65536 + 4096;
    cudaFuncSetAttribute(gemm_g3, cudaFuncAttributeMaxDynamicSharedMemorySize, SMEM_G3);
    cudaFuncSetAttribute(gemm_g4, cudaFuncAttributeMaxDynamicSharedMemorySize, SMEM_G4);
    cudaFuncSetAttribute(flash_attn, cudaFuncAttributeMaxDynamicSharedMemorySize, SMEM_F);

    // weight conversions
    conv_all<<<2048, 256>>>(memory, w1, w2, memb, w1T, w2T);

    // flash: x convert + cat0/catb0 + xmean partials + attention -> cat1/catb1
    flash_attn<<<512, 256, SMEM_F>>>(x, memb, cat, catb, xp);

    // combine xmean partials
    xmean_comb<<<64, 256>>>(xp, xmn);

    // G3: h = silu(catb @ w1T^T + b1) -> hb bf16 [65536,1024]
    gemm_g3<<<dim3(8, 512), 256, SMEM_G3>>>(catb, w1T, b1, hb, 512, 1024);

    // G4: g = sigmoid(hb @ w2T^T + b2) -> newmem (in-CTA b-reduction)
    gemm_g4<<<dim3(2, 512), 256, SMEM_G4>>>(hb, w2T, b2, memory, xmn, newmem);
}

// round 17
// speedup vs baseline: 1.1658x; 1.1658x over previous
#include <cuda_runtime.h>
#include <cuda_bf16.h>
#include <cstdint>
#include <math.h>

// ===========================================================================
// DynamicMemoryBank — R17: R12 pipeline + coalesced transposes + folded comb
//   conv: tiled 32x32 smem transposes for w1T/w2T, float4 memb copy
//   flash (R12): x convert + cat0/catb0 + xmean partials + attention
//   G3: first 64 CTAs also combine xmean partials; h = silu(catb@w1T^T+b1)
//   G4: g = sigmoid(hb@w2T^T+b2), 64b x 2m rows, in-CTA b-reduce -> newmem
// ===========================================================================

__device__ __forceinline__ uint32_t smem_u32(const void* p) {
    uint32_t a;
    asm("{ .reg .u64 t; cvta.to.shared.u64 t, %1; cvt.u32.u64 %0, t; }" : "=r"(a) : "l"(p));
    return a;
}

#define LDSM_X4(R0, R1, R2, R3, ADDR) \
    asm volatile("ldmatrix.sync.aligned.m8n8.x4.shared.b16 {%0,%1,%2,%3}, [%4];" \
        : "=r"(R0), "=r"(R1), "=r"(R2), "=r"(R3) : "r"(ADDR))

#define LDSM_X4T(R0, R1, R2, R3, ADDR) \
    asm volatile("ldmatrix.sync.aligned.m8n8.x4.trans.shared.b16 {%0,%1,%2,%3}, [%4];" \
        : "=r"(R0), "=r"(R1), "=r"(R2), "=r"(R3) : "r"(ADDR))

#define MMA16816(C, A0, A1, A2, A3, B0, B1) \
    asm volatile("mma.sync.aligned.m16n8k16.row.col.f32.bf16.bf16.f32 " \
        "{%0,%1,%2,%3}, {%4,%5,%6,%7}, {%8,%9}, {%0,%1,%2,%3};" \
        : "+f"((C)[0]), "+f"((C)[1]), "+f"((C)[2]), "+f"((C)[3]) \
        : "r"(A0), "r"(A1), "r"(A2), "r"(A3), "r"(B0), "r"(B1))

#define CP_ASYNC16(DST, SRC) \
    asm volatile("cp.async.cg.shared.global [%0], [%1], 16;" :: "r"(DST), "l"(SRC))
#define CP_COMMIT() asm volatile("cp.async.commit_group;" ::: "memory")
#define CP_WAIT(N)  asm volatile("cp.async.wait_group %0;" :: "n"(N) : "memory")

// ---------------------------------------------------------------------------
// scratch
// ---------------------------------------------------------------------------
__device__ __nv_bfloat16 g_catb[33554432];    // [65536,512]
__device__ __nv_bfloat16 g_hb[67108864];      // [65536,1024]
__device__ __nv_bfloat16 g_memb[262144];      // [1024,256]
__device__ __nv_bfloat16 g_w1T[524288];       // [1024,512]
__device__ __nv_bfloat16 g_w2T[262144];       // [256,1024]
__device__ float         g_xpart[131072];     // [512,256] xmean partials (raw sums)
__device__ float         g_xmean[16384];      // [64,256]

// swizzled addr within a 128-row x 512B tile (16B-chunk granularity)
__device__ __forceinline__ uint32_t tile_addr(uint32_t base, int r, int colbyte) {
    return base + (uint32_t)(r * 512) + (uint32_t)(colbyte & ~127)
         + (uint32_t)(((((colbyte >> 4) & 7) ^ (r & 7)) << 4));
}

// ---------------------------------------------------------------------------
// Flash kernel (R12): per CTA 128 rows of x; 8 mem chunks.
// ---------------------------------------------------------------------------
__global__ void __launch_bounds__(256, 1)
flash_attn(const float* __restrict__ x, const __nv_bfloat16* __restrict__ memb,
           float* __restrict__ cat, __nv_bfloat16* __restrict__ catb,
           float* __restrict__ xpart)
{
    extern __shared__ char dsm[];
    const uint32_t dbase = smem_u32(dsm);
    const uint32_t sbase = (dbase + 1023) & ~1023u;
    const uint32_t xs = sbase;
    const uint32_t ms[2] = { sbase + 65536, sbase + 131072 };
    char* const sptr = dsm + (sbase - dbase);

    const int tid = threadIdx.x;
    const int wid = tid >> 5, lane = tid & 31;
    const long row0 = (long)blockIdx.x * 128;

    {
        const char* Mg = (const char*)memb;
#pragma unroll
        for (int j = 0; j < 16; j++) {
            int idx = tid + j * 256;
            int r = idx >> 5;
            int colbyte = (idx & 31) << 4;
            CP_ASYNC16(tile_addr(ms[0], r, colbyte), Mg + (long)r * 512 + colbyte);
        }
        CP_COMMIT();
    }

    {
        const float4* Xg = (const float4*)x + row0 * 64;
        float4* cat4  = (float4*)cat;
        uint2*  catb2 = (uint2*)catb;
        float4 csum = make_float4(0.f, 0.f, 0.f, 0.f);
#pragma unroll 8
        for (int it = 0; it < 32; it++) {
            int idx = it * 256 + tid;
            int r = idx >> 6;
            int c4 = idx & 63;
            float4 v = Xg[idx];
            cat4[(row0 + r) * 128 + c4] = v;
            __nv_bfloat162 lo = __float22bfloat162_rn(make_float2(v.x, v.y));
            __nv_bfloat162 hi = __float22bfloat162_rn(make_float2(v.z, v.w));
            uint2 pk = make_uint2(*reinterpret_cast<uint32_t*>(&lo),
                                  *reinterpret_cast<uint32_t*>(&hi));
            catb2[(row0 + r) * 128 + c4] = pk;
            int colbyte = c4 * 8;
            uint32_t addr = tile_addr(xs, r, colbyte & ~15) + (colbyte & 8);
            *(uint2*)(dsm + (addr - dbase)) = pk;
            csum.x += v.x; csum.y += v.y; csum.z += v.z; csum.w += v.w;
        }
        float4* red = (float4*)(sptr + 196608);
        red[tid] = csum;
        __syncthreads();
        if (tid < 64) {
            float4 a = red[tid], b = red[tid + 64], c = red[tid + 128], d = red[tid + 192];
            float4 s = make_float4(a.x + b.x + c.x + d.x, a.y + b.y + c.y + d.y,
                                   a.z + b.z + c.z + d.z, a.w + b.w + c.w + d.w);
            ((float4*)xpart)[blockIdx.x * 64 + tid] = s;
        }
    }

    float acc_o[32][4];
#pragma unroll
    for (int b = 0; b < 32; b++)
#pragma unroll
        for (int q = 0; q < 4; q++) acc_o[b][q] = 0.0f;
    float m0 = -1e30f, m1 = -1e30f, l0 = 0.0f, l1 = 0.0f;

    for (int c = 0; c < 8; c++) {
        const int b = c & 1;
        if (c + 1 < 8) {
            const char* Mg = (const char*)(memb + (long)(c + 1) * 128 * 256);
#pragma unroll
            for (int j = 0; j < 16; j++) {
                int idx = tid + j * 256;
                int r = idx >> 5;
                int colbyte = (idx & 31) << 4;
                CP_ASYNC16(tile_addr(ms[1 - b], r, colbyte), Mg + (long)r * 512 + colbyte);
            }
            CP_COMMIT();
            CP_WAIT(1);
        } else {
            CP_WAIT(0);
        }
        __syncthreads();

        float acc_s[16][4];
#pragma unroll
        for (int nb = 0; nb < 16; nb++)
#pragma unroll
            for (int q = 0; q < 4; q++) acc_s[nb][q] = 0.0f;

#pragma unroll
        for (int ks = 0; ks < 16; ks++) {
            uint32_t a0, a1, a2, a3;
            {
                int r = 16 * wid + (lane & 15);
                int colbyte = ks * 32 + ((lane >> 4) << 4);
                LDSM_X4(a0, a1, a2, a3, tile_addr(xs, r, colbyte));
            }
#pragma unroll
            for (int nb2 = 0; nb2 < 8; nb2++) {
                uint32_t d0, d1, d2, d3;
                int rn = nb2 * 16 + (lane & 7) + ((lane >> 4) << 3);
                int colbyte = ks * 32 + (((lane >> 3) & 1) << 4);
                LDSM_X4(d0, d1, d2, d3, tile_addr(ms[b], rn, colbyte));
                MMA16816(acc_s[nb2 * 2],     a0, a1, a2, a3, d0, d1);
                MMA16816(acc_s[nb2 * 2 + 1], a0, a1, a2, a3, d2, d3);
            }
        }

        float rm0 = -1e30f, rm1 = -1e30f;
#pragma unroll
        for (int nb = 0; nb < 16; nb++) {
            rm0 = fmaxf(rm0, fmaxf(acc_s[nb][0], acc_s[nb][1]));
            rm1 = fmaxf(rm1, fmaxf(acc_s[nb][2], acc_s[nb][3]));
        }
        rm0 = fmaxf(rm0, __shfl_xor_sync(0xffffffffu, rm0, 1));
        rm0 = fmaxf(rm0, __shfl_xor_sync(0xffffffffu, rm0, 2));
        rm1 = fmaxf(rm1, __shfl_xor_sync(0xffffffffu, rm1, 1));
        rm1 = fmaxf(rm1, __shfl_xor_sync(0xffffffffu, rm1, 2));

        float mn0 = fmaxf(m0, rm0), mn1 = fmaxf(m1, rm1);
        float sc0 = __expf(m0 - mn0), sc1 = __expf(m1 - mn1);
        m0 = mn0; m1 = mn1;

        uint32_t pk[16], qk[16];
        float ls0 = 0.0f, ls1 = 0.0f;
#pragma unroll
        for (int nb = 0; nb < 16; nb++) {
            float e0 = __expf(acc_s[nb][0] - mn0);
            float e1 = __expf(acc_s[nb][1] - mn0);
            float e2 = __expf(acc_s[nb][2] - mn1);
            float e3 = __expf(acc_s[nb][3] - mn1);
            ls0 += e0 + e1; ls1 += e2 + e3;
            __nv_bfloat162 h0 = __float22bfloat162_rn(make_float2(e0, e1));
            __nv_bfloat162 h1 = __float22bfloat162_rn(make_float2(e2, e3));
            pk[nb] = *reinterpret_cast<uint32_t*>(&h0);
            qk[nb] = *reinterpret_cast<uint32_t*>(&h1);
        }
        ls0 += __shfl_xor_sync(0xffffffffu, ls0, 1);
        ls0 += __shfl_xor_sync(0xffffffffu, ls0, 2);
        ls1 += __shfl_xor_sync(0xffffffffu, ls1, 1);
        ls1 += __shfl_xor_sync(0xffffffffu, ls1, 2);
        l0 = l0 * sc0 + ls0;
        l1 = l1 * sc1 + ls1;

#pragma unroll
        for (int nb = 0; nb < 32; nb++) {
            acc_o[nb][0] *= sc0; acc_o[nb][1] *= sc0;
            acc_o[nb][2] *= sc1; acc_o[nb][3] *= sc1;
        }

#pragma unroll
        for (int j = 0; j < 8; j++) {
            uint32_t a0 = pk[2 * j], a1 = qk[2 * j], a2 = pk[2 * j + 1], a3 = qk[2 * j + 1];
#pragma unroll
            for (int on = 0; on < 16; on++) {
                uint32_t d0, d1, d2, d3;
                int grp = lane >> 3;
                int rv = 16 * j + ((grp & 1) << 3) + (lane & 7);
                int colbyte = on * 32 + ((grp >> 1) << 4);
                LDSM_X4T(d0, d1, d2, d3, tile_addr(ms[b], rv, colbyte));
                MMA16816(acc_o[on * 2],     a0, a1, a2, a3, d0, d1);
                MMA16816(acc_o[on * 2 + 1], a0, a1, a2, a3, d2, d3);
            }
        }
        __syncthreads();
    }

    float inv0 = 1.0f / l0, inv1 = 1.0f / l1;
    long r0 = row0 + 16 * wid + (lane >> 2);
    long r1 = r0 + 8;
#pragma unroll
    for (int nb = 0; nb < 32; nb++) {
        int cn = 256 + nb * 8 + (lane & 3) * 2;
        float v0 = acc_o[nb][0] * inv0, v1 = acc_o[nb][1] * inv0;
        float v2 = acc_o[nb][2] * inv1, v3 = acc_o[nb][3] * inv1;
        *(float2*)(cat + r0 * 512 + cn) = make_float2(v0, v1);
        *(float2*)(cat + r1 * 512 + cn) = make_float2(v2, v3);
        __nv_bfloat162 h0 = __float22bfloat162_rn(make_float2(v0, v1));
        __nv_bfloat162 h1 = __float22bfloat162_rn(make_float2(v2, v3));
        *(uint32_t*)(catb + r0 * 512 + cn) = *reinterpret_cast<uint32_t*>(&h0);
        *(uint32_t*)(catb + r1 * 512 + cn) = *reinterpret_cast<uint32_t*>(&h1);
    }
}

// ---------------------------------------------------------------------------
// G3: h = silu(catb @ w1T^T + b1) -> bf16. R12 2-stage pipeline.
// First 64 CTAs also combine xmean partials (hidden under first wave).
// ---------------------------------------------------------------------------
__global__ void __launch_bounds__(256, 2)
gemm_g3(const __nv_bfloat16* __restrict__ A, const __nv_bfloat16* __restrict__ B,
        const float* __restrict__ bias, __nv_bfloat16* __restrict__ Cb,
        int K, int ldcb, const float* __restrict__ xpart, float* __restrict__ xmn)
{
    extern __shared__ char dsm[];
    const uint32_t sbase = (smem_u32(dsm) + 1023) & ~1023u;
    const int tid = threadIdx.x;
    const int wid = tid >> 5, lane = tid & 31;
    const int wm = wid & 3;
    const int wn = wid >> 2;
    const long row0 = (long)blockIdx.y * 128;
    const long col0 = (long)blockIdx.x * 128;

    // folded xmean combine: first 64 CTAs, independent global work
    {
        int cid = blockIdx.y * 8 + blockIdx.x;
        if (cid < 64) {
            int i = cid * 256 + tid;
            int b = i >> 8, c = i & 255;
            float s = 0.0f;
#pragma unroll
            for (int k = 0; k < 8; k++) s += xpart[(b * 8 + k) * 256 + c];
            xmn[i] = s * (1.0f / 1024.0f);
        }
    }

    const uint32_t sA[2] = { sbase,         sbase + 32768 };
    const uint32_t sB[2] = { sbase + 16384, sbase + 49152 };

    float acc[2][8][4];
#pragma unroll
    for (int i = 0; i < 2; i++)
#pragma unroll
        for (int j = 0; j < 8; j++)
#pragma unroll
            for (int q = 0; q < 4; q++) acc[i][j][q] = 0.0f;

    const char* Ag = (const char*)(A + row0 * K);
    const char* Bg = (const char*)(B + col0 * K);
    const long rowb = (long)K * 2;
    const int lr = tid >> 3;
    const int lc = tid & 7;
    const int nchunks = K >> 6;

    {
#pragma unroll
        for (int j = 0; j < 4; j++) {
            int r = lr + j * 32;
            uint32_t off = (uint32_t)(r * 128) + (uint32_t)((lc ^ (r & 7)) << 4);
            CP_ASYNC16(sA[0] + off, Ag + (long)r * rowb + lc * 16);
            CP_ASYNC16(sB[0] + off, Bg + (long)r * rowb + lc * 16);
        }
        CP_COMMIT();
    }

    for (int i = 0; i < nchunks; i++) {
        const int b = i & 1;
        if (i + 1 < nchunks) {
            const long kb = (long)(i + 1) << 7;
#pragma unroll
            for (int j = 0; j < 4; j++) {
                int r = lr + j * 32;
                uint32_t off = (uint32_t)(r * 128) + (uint32_t)((lc ^ (r & 7)) << 4);
                CP_ASYNC16(sA[1 - b] + off, Ag + (long)r * rowb + kb + lc * 16);
                CP_ASYNC16(sB[1 - b] + off, Bg + (long)r * rowb + kb + lc * 16);
            }
            CP_COMMIT();
            CP_WAIT(1);
        } else {
            CP_WAIT(0);
        }
        __syncthreads();

#pragma unroll
        for (int ks = 0; ks < 4; ks++) {
            uint32_t af[2][4];
#pragma unroll
            for (int mi = 0; mi < 2; mi++) {
                int r = wm * 32 + mi * 16 + (lane & 15);
                int cch = ks * 2 + (lane >> 4);
                uint32_t addr = sA[b] + (uint32_t)(r * 128) + (uint32_t)((cch ^ (r & 7)) << 4);
                LDSM_X4(af[mi][0], af[mi][1], af[mi][2], af[mi][3], addr);
            }
            uint32_t bf[4][4];
#pragma unroll
            for (int nt = 0; nt < 4; nt++) {
                int r = wn * 64 + nt * 16 + (lane & 7) + ((lane >> 4) << 3);
                int cch = ks * 2 + ((lane >> 3) & 1);
                uint32_t addr = sB[b] + (uint32_t)(r * 128) + (uint32_t)((cch ^ (r & 7)) << 4);
                LDSM_X4(bf[nt][0], bf[nt][1], bf[nt][2], bf[nt][3], addr);
            }
#pragma unroll
            for (int mi = 0; mi < 2; mi++)
#pragma unroll
                for (int ni = 0; ni < 8; ni++) {
                    uint32_t b0 = bf[ni >> 1][(ni & 1) * 2];
                    uint32_t b1 = bf[ni >> 1][(ni & 1) * 2 + 1];
                    MMA16816(acc[mi][ni], af[mi][0], af[mi][1], af[mi][2], af[mi][3], b0, b1);
                }
        }
        __syncthreads();
    }

#pragma unroll
    for (int mi = 0; mi < 2; mi++) {
#pragma unroll
        for (int h = 0; h < 2; h++) {
            long r = row0 + wm * 32 + mi * 16 + (lane >> 2) + h * 8;
#pragma unroll
            for (int ni = 0; ni < 8; ni++) {
                int cn = (int)col0 + wn * 64 + ni * 8 + (lane & 3) * 2;
                float v0 = acc[mi][ni][h * 2]     + bias[cn];
                float v1 = acc[mi][ni][h * 2 + 1] + bias[cn + 1];
                v0 = v0 / (1.0f + __expf(-v0));
                v1 = v1 / (1.0f + __expf(-v1));
                __nv_bfloat162 h2 = __float22bfloat162_rn(make_float2(v0, v1));
                *(uint32_t*)(Cb + r * ldcb + cn) = *reinterpret_cast<uint32_t*>(&h2);
            }
        }
    }
}

// ---------------------------------------------------------------------------
// G4: g = sigmoid(hb @ w2T^T + b2), 128 rows (64 b x 2 m) x 128 c tile.
// R12 2-stage pipeline. In-CTA b-reduce -> newmem direct.
// ---------------------------------------------------------------------------
__global__ void __launch_bounds__(256, 2)
gemm_g4(const __nv_bfloat16* __restrict__ A, const __nv_bfloat16* __restrict__ B,
        const float* __restrict__ bias,
        const float* __restrict__ mem, const float* __restrict__ xm,
        float* __restrict__ nm)
{
    extern __shared__ char dsm[];
    const uint32_t sbase = (smem_u32(dsm) + 1023) & ~1023u;
    const int tid = threadIdx.x;
    const int wid = tid >> 5, lane = tid & 31;
    const int wm = wid & 3;
    const int wn = wid >> 2;
    const int m0 = blockIdx.y * 2;
    const int col0 = blockIdx.x * 128;
    const int K = 1024;

    const uint32_t sA[2] = { sbase,         sbase + 32768 };
    const uint32_t sB[2] = { sbase + 16384, sbase + 49152 };

    float acc[2][8][4];
#pragma unroll
    for (int i = 0; i < 2; i++)
#pragma unroll
        for (int j = 0; j < 8; j++)
#pragma unroll
            for (int q = 0; q < 4; q++) acc[i][j][q] = 0.0f;

    const char* Ag = (const char*)A;
    const char* Bg = (const char*)(B + (long)col0 * K);
    const long rowb = (long)K * 2;
    const int lr = tid >> 3;
    const int lc = tid & 7;
    const int nchunks = K >> 6;

#pragma unroll
    for (int j = 0; j < 4; j++) {
        int i = lr + j * 32;
        long gr = ((long)(i & 63) << 10) + m0 + (i >> 6);
        uint32_t off = (uint32_t)(i * 128) + (uint32_t)((lc ^ (i & 7)) << 4);
        CP_ASYNC16(sA[0] + off, Ag + gr * rowb + lc * 16);
        CP_ASYNC16(sB[0] + off, Bg + (long)i * rowb + lc * 16);
    }
    CP_COMMIT();

    for (int it = 0; it < nchunks; it++) {
        const int b = it & 1;
        if (it + 1 < nchunks) {
            const long kb = (long)(it + 1) << 7;
#pragma unroll
            for (int j = 0; j < 4; j++) {
                int i = lr + j * 32;
                long gr = ((long)(i & 63) << 10) + m0 + (i >> 6);
                uint32_t off = (uint32_t)(i * 128) + (uint32_t)((lc ^ (i & 7)) << 4);
                CP_ASYNC16(sA[1 - b] + off, Ag + gr * rowb + kb + lc * 16);
                CP_ASYNC16(sB[1 - b] + off, Bg + (long)i * rowb + kb + lc * 16);
            }
            CP_COMMIT();
            CP_WAIT(1);
        } else {
            CP_WAIT(0);
        }
        __syncthreads();

#pragma unroll
        for (int ks = 0; ks < 4; ks++) {
            uint32_t af[2][4];
#pragma unroll
            for (int mi = 0; mi < 2; mi++) {
                int r = wm * 32 + mi * 16 + (lane & 15);
                int cch = ks * 2 + (lane >> 4);
                uint32_t addr = sA[b] + (uint32_t)(r * 128) + (uint32_t)((cch ^ (r & 7)) << 4);
                LDSM_X4(af[mi][0], af[mi][1], af[mi][2], af[mi][3], addr);
            }
            uint32_t bf[4][4];
#pragma unroll
            for (int nt = 0; nt < 4; nt++) {
                int r = wn * 64 + nt * 16 + (lane & 7) + ((lane >> 4) << 3);
                int cch = ks * 2 + ((lane >> 3) & 1);
                uint32_t addr = sB[b] + (uint32_t)(r * 128) + (uint32_t)((cch ^ (r & 7)) << 4);
                LDSM_X4(bf[nt][0], bf[nt][1], bf[nt][2], bf[nt][3], addr);
            }
#pragma unroll
            for (int mi = 0; mi < 2; mi++)
#pragma unroll
                for (int ni = 0; ni < 8; ni++) {
                    uint32_t b0 = bf[ni >> 1][(ni & 1) * 2];
                    uint32_t b1 = bf[ni >> 1][(ni & 1) * 2 + 1];
                    MMA16816(acc[mi][ni], af[mi][0], af[mi][1], af[mi][2], af[mi][3], b0, b1);
                }
        }
        __syncthreads();
    }

    // ---- epilogue: blend into padded smem (528B rows), reduce over b ----
#pragma unroll
    for (int mi = 0; mi < 2; mi++) {
#pragma unroll
        for (int h = 0; h < 2; h++) {
            int il = wm * 32 + mi * 16 + (lane >> 2) + h * 8;
            int bb = il & 63;
            int mloc = il >> 6;
#pragma unroll
            for (int ni = 0; ni < 8; ni++) {
                int cl = wn * 64 + ni * 8 + (lane & 3) * 2;
                int cn = col0 + cl;
                float v0 = acc[mi][ni][h * 2]     + bias[cn];
                float v1 = acc[mi][ni][h * 2 + 1] + bias[cn + 1];
                float g0 = 1.0f / (1.0f + __expf(-v0));
                float g1 = 1.0f / (1.0f + __expf(-v1));
                float mm0 = mem[(m0 + mloc) * 256 + cn];
                float mm1 = mem[(m0 + mloc) * 256 + cn + 1];
                float xv0 = xm[bb * 256 + cn];
                float xv1 = xm[bb * 256 + cn + 1];
                float o0 = fmaf(xv0 - mm0, g0, mm0) * (1.0f / 64.0f);
                float o1 = fmaf(xv1 - mm1, g1, mm1) * (1.0f / 64.0f);
                *(float2*)(dsm + (sbase - smem_u32(dsm)) + il * 528 + cl * 4) = make_float2(o0, o1);
            }
        }
    }
    __syncthreads();

    {
        int mloc = tid >> 7;
        int c = tid & 127;
        const char* sred = dsm + (sbase - smem_u32(dsm));
        float s = 0.0f;
#pragma unroll
        for (int k = 0; k < 64; k++) {
            int il = mloc * 64 + k;
            s += *(const float*)(sred + il * 528 + c * 4);
        }
        nm[(m0 + mloc) * 256 + col0 + c] = s;
    }
}

// ---------------------------------------------------------------------------
// conv: coalesced transposes (32x32 smem tiles) + float4 memb copy.
// grid 1024: tiles 0..511 = w1 (16 x 32), 512..767 = w2 (32 x 8),
//            768..1023 = memb copy (256 blocks x 1024 elems)
// ---------------------------------------------------------------------------
__global__ void conv_all(const float* __restrict__ mem, const float* __restrict__ w1,
                         const float* __restrict__ w2,
                         __nv_bfloat16* __restrict__ memb, __nv_bfloat16* __restrict__ w1T,
                         __nv_bfloat16* __restrict__ w2T)
{
    __shared__ float t[32][33];
    const int tid = threadIdx.x;
    const int tx = tid & 31, ty = tid >> 5;   // ty 0..7
    const int tile = blockIdx.x;

    if (tile < 512) {            // w1 [512,1024] -> w1T [1024,512]
        int tr = tile >> 5, tc = tile & 31;   // tr over k (16), tc over n (32)
#pragma unroll
        for (int j = 0; j < 4; j++) {
            int k = tr * 32 + ty + j * 8;
            int n = tc * 32 + tx;
            t[ty + j * 8][tx] = w1[k * 1024 + n];
        }
        __syncthreads();
#pragma unroll
        for (int j = 0; j < 4; j++) {
            int n = tc * 32 + ty + j * 8;
            int k = tr * 32 + tx;
            w1T[n * 512 + k] = __float2bfloat16(t[tx][ty + j * 8]);
        }
    } else if (tile < 768) {     // w2 [1024,256] -> w2T [256,1024]
        int tt = tile - 512;
        int tr = tt >> 3, tc = tt & 7;        // tr over f (32), tc over c (8)
#pragma unroll
        for (int j = 0; j < 4; j++) {
            int f = tr * 32 + ty + j * 8;
            int c = tc * 32 + tx;
            t[ty + j * 8][tx] = w2[f * 256 + c];
        }
        __syncthreads();
#pragma unroll
        for (int j = 0; j < 4; j++) {
            int c = tc * 32 + ty + j * 8;
            int f = tr * 32 + tx;
            w2T[c * 1024 + f] = __float2bfloat16(t[tx][ty + j * 8]);
        }
    } else {                     // memb: bf16 copy of mem
        int i4 = (tile - 768) * 256 + tid;    // 0..65535 float4s
        float4 v = ((const float4*)mem)[i4];
        __nv_bfloat162 lo = __float22bfloat162_rn(make_float2(v.x, v.y));
        __nv_bfloat162 hi = __float22bfloat162_rn(make_float2(v.z, v.w));
        uint2 pk = make_uint2(*reinterpret_cast<uint32_t*>(&lo),
                              *reinterpret_cast<uint32_t*>(&hi));
        ((uint2*)memb)[i4] = pk;
    }
}

// ---------------------------------------------------------------------------
extern "C" void kernel_launch(void* const* d_in, const int* in_sizes, int n_in,
                              void* d_out, int out_size)
{
    const float* x      = (const float*)d_in[0];
    const float* memory = (const float*)d_in[1];
    const float* w1     = (const float*)d_in[2];
    const float* b1     = (const float*)d_in[3];
    const float* w2     = (const float*)d_in[4];
    const float* b2     = (const float*)d_in[5];

    float* out    = (float*)d_out;
    float* cat    = out;               // [65536,512]
    float* newmem = out + 33554432ll;  // [1024,256]

    __nv_bfloat16 *catb, *hb, *memb, *w1T, *w2T;
    float *xp, *xmn;
    cudaGetSymbolAddress((void**)&catb, g_catb);
    cudaGetSymbolAddress((void**)&hb, g_hb);
    cudaGetSymbolAddress((void**)&memb, g_memb);
    cudaGetSymbolAddress((void**)&w1T, g_w1T);
    cudaGetSymbolAddress((void**)&w2T, g_w2T);
    cudaGetSymbolAddress((void**)&xp, g_xpart);
    cudaGetSymbolAddress((void**)&xmn, g_xmean);

    const int SMEM_G3 = 1024 + 65536;           // guard + 2x(16KB+16KB)
    const int SMEM_G4 = 1024 + 128 * 528;       // guard + max(tiles, reduce buf)
    const int SMEM_F  = 1024 + 3 * 65536 + 4096;
    cudaFuncSetAttribute(gemm_g3, cudaFuncAttributeMaxDynamicSharedMemorySize, SMEM_G3);
    cudaFuncSetAttribute(gemm_g4, cudaFuncAttributeMaxDynamicSharedMemorySize, SMEM_G4);
    cudaFuncSetAttribute(flash_attn, cudaFuncAttributeMaxDynamicSharedMemorySize, SMEM_F);

    // weight conversions (coalesced transposes)
    conv_all<<<1024, 256>>>(memory, w1, w2, memb, w1T, w2T);

    // flash: x convert + cat0/catb0 + xmean partials + attention -> cat1/catb1
    flash_attn<<<512, 256, SMEM_F>>>(x, memb, cat, catb, xp);

    // G3: h = silu(catb @ w1T^T + b1) -> hb bf16; first 64 CTAs combine xmean
    gemm_g3<<<dim3(8, 512), 256, SMEM_G3>>>(catb, w1T, b1, hb, 512, 1024, xp, xmn);

    // G4: g = sigmoid(hb @ w2T^T + b2) -> newmem (in-CTA b-reduction)
    gemm_g4<<<dim3(2, 512), 256, SMEM_G4>>>(hb, w2T, b2, memory, xmn, newmem);
}